// round 2
// baseline (speedup 1.0000x reference)
#include <cuda_runtime.h>

// TritonDualLIF: x [T=16,B=32,N=196,C=512] f32, decay scalar.
// v = d*v + x[t]; vpool[t,b,c] = mean_n(pre-reset v); s = (v>=1); v = s?0:v.
// out = spikes [T,B,N,C] ++ vpool [T,B,C].

#define T_ 16
#define B_ 32
#define N_ 196
#define C_ 512
#define C4 (C_ / 4)        // 128 float4 per row
#define NH 4               // N split into 4 chunks
#define NSUB 49            // 196 / 4
#define NLANES 8
#define JMAX 7             // ceil(49/8); j==6 only for ty==0 (48+1=49)

// Per-chunk partial sums: [NH][T][B][C4] float4 = 4 MB static scratch.
__device__ float4 g_partial[NH * T_ * B_ * C4];

__global__ __launch_bounds__(256, 4)
void lif_main(const float4* __restrict__ x,
              const float* __restrict__ decay,
              float4* __restrict__ spikes) {
    const int tx   = threadIdx.x;     // 0..31 -> c4 lane
    const int ty   = threadIdx.y;     // 0..7  -> n lane
    const int cblk = blockIdx.x;      // 0..3
    const int b    = blockIdx.y;      // 0..31
    const int nh   = blockIdx.z;      // 0..3
    const float d  = decay[0];

    const unsigned c4    = (unsigned)cblk * 32u + (unsigned)tx;
    const unsigned nbase = (unsigned)(nh * NSUB + ty);

    __shared__ float4 red[NLANES][32];

    float4 v[JMAX];
#pragma unroll
    for (int j = 0; j < JMAX; ++j) v[j] = make_float4(0.f, 0.f, 0.f, 0.f);

    const unsigned base    = (unsigned)b * (N_ * C4) + nbase * C4 + c4;
    const unsigned tstride = (unsigned)(B_ * N_ * C4);
    // thread does 7 j-iters iff ty==0 (covers n_local 48), else 6
    const int jcnt = (ty == 0) ? JMAX : (JMAX - 1);

    for (int t = 0; t < T_; ++t) {
        const unsigned tb = (unsigned)t * tstride + base;
        float4 part = make_float4(0.f, 0.f, 0.f, 0.f);
#pragma unroll
        for (int j = 0; j < JMAX; ++j) {
            if (j < jcnt) {
                const unsigned idx = tb + (unsigned)(j * (NLANES * C4));
                const float4 xv = __ldcs(&x[idx]);
                float4 vv;
                vv.x = fmaf(d, v[j].x, xv.x);
                vv.y = fmaf(d, v[j].y, xv.y);
                vv.z = fmaf(d, v[j].z, xv.z);
                vv.w = fmaf(d, v[j].w, xv.w);
                part.x += vv.x; part.y += vv.y;
                part.z += vv.z; part.w += vv.w;
                float4 s;
                s.x = (vv.x >= 1.f) ? 1.f : 0.f;
                s.y = (vv.y >= 1.f) ? 1.f : 0.f;
                s.z = (vv.z >= 1.f) ? 1.f : 0.f;
                s.w = (vv.w >= 1.f) ? 1.f : 0.f;
                __stcs(&spikes[idx], s);
                v[j].x = (vv.x >= 1.f) ? 0.f : vv.x;
                v[j].y = (vv.y >= 1.f) ? 0.f : vv.y;
                v[j].z = (vv.z >= 1.f) ? 0.f : vv.z;
                v[j].w = (vv.w >= 1.f) ? 0.f : vv.w;
            }
        }
        red[ty][tx] = part;
        __syncthreads();
        if (ty == 0) {
            float4 sum = red[0][tx];
#pragma unroll
            for (int k = 1; k < NLANES; ++k) {
                sum.x += red[k][tx].x;
                sum.y += red[k][tx].y;
                sum.z += red[k][tx].z;
                sum.w += red[k][tx].w;
            }
            g_partial[((unsigned)(nh * T_ + t) * B_ + (unsigned)b) * C4 + c4] = sum;
        }
        if (t != T_ - 1) __syncthreads();
    }
}

__global__ __launch_bounds__(256)
void lif_pool(float4* __restrict__ vpool) {
    const unsigned i = blockIdx.x * 256u + threadIdx.x;  // 0 .. T*B*C4-1
    const unsigned sz = (unsigned)(T_ * B_ * C4);
    if (i < sz) {
        float4 a = g_partial[i];
        float4 b = g_partial[sz + i];
        float4 c = g_partial[2u * sz + i];
        float4 e = g_partial[3u * sz + i];
        const float inv = 1.0f / (float)N_;
        float4 r;
        r.x = (a.x + b.x + c.x + e.x) * inv;
        r.y = (a.y + b.y + c.y + e.y) * inv;
        r.z = (a.z + b.z + c.z + e.z) * inv;
        r.w = (a.w + b.w + c.w + e.w) * inv;
        vpool[i] = r;
    }
}

extern "C" void kernel_launch(void* const* d_in, const int* in_sizes, int n_in,
                              void* d_out, int out_size) {
    const float4* x    = (const float4*)d_in[0];
    const float* decay = (const float*)d_in[1];
    float* out = (float*)d_out;

    float4* spikes = (float4*)out;
    float4* vpool  = (float4*)(out + (size_t)T_ * B_ * N_ * C_);

    dim3 block(32, NLANES);            // 256 threads
    dim3 grid(C4 / 32, B_, NH);        // 4 x 32 x 4 = 512 blocks
    lif_main<<<grid, block>>>(x, decay, spikes);

    const unsigned pool_elems = T_ * B_ * C4;           // 65536 float4
    lif_pool<<<(pool_elems + 255) / 256, 256>>>(vpool);
}

// round 3
// speedup vs baseline: 1.0806x; 1.0806x over previous
#include <cuda_runtime.h>

// TritonDualLIF: x [T=16,B=32,N=196,C=512] f32, decay scalar.
// v = d*v + x[t]; vpool[t,b,c] = mean_n(pre-reset v); s = (v>=1); v = s?0:v.
// out = spikes [T,B,N,C] ++ vpool [T,B,C].
//
// Barrier-free main loop: per-thread partial sums land in exclusive smem
// slots; a single __syncthreads after the T-loop precedes the reduction.

#define T_ 16
#define B_ 32
#define N_ 196
#define C_ 512
#define NLANES 8
#define JMAX 25   // ceil(196/8); lanes ty<4 do 25, ty>=4 do 24 (4*25+4*24=196)

__global__ __launch_bounds__(256, 3)
void lif_dual_kernel(const float* __restrict__ x,
                     const float* __restrict__ decay,
                     float* __restrict__ out) {
    const int tx   = threadIdx.x;     // c within 32-wide tile
    const int ty   = threadIdx.y;     // n lane, 0..7
    const int cblk = blockIdx.x;      // 0..15
    const int b    = blockIdx.y;      // 0..31
    const int c    = cblk * 32 + tx;
    const float d  = decay[0];

    float* __restrict__ spikes = out;
    float* __restrict__ vpool  = out + (size_t)T_ * B_ * N_ * C_;

    // red[ty][t][tx] : exclusive per-thread slot per timestep -> no sync in loop
    __shared__ float red[NLANES][T_][32];

    float v[JMAX];
#pragma unroll
    for (int j = 0; j < JMAX; ++j) v[j] = 0.0f;

    const unsigned bbase   = (unsigned)b * (N_ * C_) + (unsigned)ty * C_ + (unsigned)c;
    const unsigned tstride = (unsigned)(B_ * N_ * C_);
    // n = ty + j*8 < 196  ->  j < (196 - ty + 7)/8 : ty 0..3 -> 25, ty 4..7 -> 24
    const int jcnt = (ty < 4) ? JMAX : (JMAX - 1);

    for (int t = 0; t < T_; ++t) {
        const unsigned tb = (unsigned)t * tstride + bbase;
        float partial = 0.0f;
#pragma unroll
        for (int j = 0; j < JMAX; ++j) {
            if (j < jcnt) {
                const unsigned idx = tb + (unsigned)(j * (NLANES * C_));
                const float xv = x[idx];
                const float vv = fmaf(d, v[j], xv);
                partial += vv;                        // pre-reset membrane
                const bool fire = (vv >= 1.0f);
                spikes[idx] = fire ? 1.0f : 0.0f;
                v[j] = fire ? 0.0f : vv;              // hard reset
            }
        }
        red[ty][t][tx] = partial;                     // exclusive slot, no race
    }

    __syncthreads();                                  // the ONLY barrier

    // 512 outputs (t,c-lane) per block, 256 threads -> 2 each.
    const int tid = ty * 32 + tx;
#pragma unroll
    for (int o = 0; o < 2; ++o) {
        const int oi = tid + o * 256;                 // 0..511
        const int t  = oi >> 5;                       // 0..15
        const int cc = oi & 31;                       // 0..31
        float sum = 0.0f;
#pragma unroll
        for (int k = 0; k < NLANES; ++k) sum += red[k][t][cc];
        vpool[(unsigned)t * (B_ * C_) + (unsigned)b * C_ + (unsigned)(cblk * 32 + cc)]
            = sum * (1.0f / (float)N_);
    }
}

extern "C" void kernel_launch(void* const* d_in, const int* in_sizes, int n_in,
                              void* d_out, int out_size) {
    const float* x     = (const float*)d_in[0];
    const float* decay = (const float*)d_in[1];
    float* out = (float*)d_out;

    dim3 block(32, NLANES);         // 256 threads
    dim3 grid(C_ / 32, B_);         // 16 x 32 = 512 blocks
    lif_dual_kernel<<<grid, block>>>(x, decay, out);
}